// round 13
// baseline (speedup 1.0000x reference)
#include <cuda_runtime.h>
#include <cuda_bf16.h>
#include <float.h>
#include <math.h>

// Problem constants
#define BB 8
#define NN 4096
#define CC 64
#define KK 30
#define E_TOT (BB*NN*KK)          // 983040
#define EPB   1024                // elements per block in F kernels (256 thr x 4)
#define NBLK2 (E_TOT/EPB)         // 960
#define NBLKK (BB*NN/8)           // 4096 knn blocks (8 rows/block)

// ---------------- scratch (device globals; no runtime allocation) ----------------
__device__ int   g_idx[E_TOT];                 // neighbor indices [B,N,K]
__device__ float g_h1[6*(size_t)E_TOT];        // layer1 pre-activations, SoA
__device__ float g_a2[3*(size_t)E_TOT];        // layer2 pre-activations, SoA
__device__ float g_a3[E_TOT];                  // layer3 pre-activations
__device__ float g_xT[(size_t)BB*NN*CC];       // x transposed to [B,N,C]
// partials transposed: [stat][block]
__device__ float g_part1[12*NBLKK];
__device__ float g_part2[6*NBLK2];
__device__ float g_part3[2*NBLK2];
__device__ float g_bn[20];  // [0:6) sc1 [6:12) sh1 [12:15) sc2 [15:18) sh2 [18] sc3 [19] sh3
__device__ unsigned g_cnt1 = 0, g_cnt2 = 0, g_cnt3 = 0;

// ---------------- helpers ----------------
__device__ __forceinline__ float2 blockReduceSum2(float a, float b, float2* sh) {
    #pragma unroll
    for (int o = 16; o; o >>= 1) {
        a += __shfl_down_sync(0xffffffffu, a, o);
        b += __shfl_down_sync(0xffffffffu, b, o);
    }
    int w = threadIdx.x >> 5;
    if ((threadIdx.x & 31) == 0) sh[w] = make_float2(a, b);
    __syncthreads();
    float2 r = make_float2(0.f, 0.f);
    if (w == 0) {
        if (threadIdx.x < 8) r = sh[threadIdx.x];
        #pragma unroll
        for (int o = 4; o; o >>= 1) {
            r.x += __shfl_down_sync(0xffffffffu, r.x, o);
            r.y += __shfl_down_sync(0xffffffffu, r.y, o);
        }
    }
    __syncthreads();
    return r;  // valid in thread 0
}

__device__ __forceinline__ float lrelu(float x) { return x > 0.f ? x : 0.2f * x; }

// Last-block finalize: reduce `nstat` partial rows of length `nblk` (fixed order,
// deterministic), compute BN scale/shift for `nch` channels into g_bn[off..].
__device__ __forceinline__ void finalize_bn(const float* part, int nblk, int nstat,
                                            int nch, int off,
                                            const float* gamma, const float* beta,
                                            float* tot /* shared[12] */) {
    __threadfence();
    int w = threadIdx.x >> 5, lane = threadIdx.x & 31;
    for (int st = w; st < nstat; st += 8) {
        const float* p = part + (size_t)st * nblk;
        float s = 0.f;
        for (int i = lane; i < nblk; i += 32) s += p[i];
        #pragma unroll
        for (int o = 16; o; o >>= 1) s += __shfl_down_sync(0xffffffffu, s, o);
        if (lane == 0) tot[st] = s;
    }
    __syncthreads();
    if (threadIdx.x < nch) {
        float inv = 1.f / (float)E_TOT;
        float mu  = tot[threadIdx.x] * inv;
        float var = tot[nch + threadIdx.x] * inv - mu * mu;
        float sc  = gamma[threadIdx.x] * rsqrtf(var + 1e-5f);
        g_bn[off + threadIdx.x] = sc;
        g_bn[off + nch + threadIdx.x] = beta[threadIdx.x] - mu * sc;
    }
}

// ---------------- transpose x: [B,C,N] -> [B,N,C] ----------------
__global__ void transpose_kernel(const float* __restrict__ x) {
    __shared__ float tile[32][33];
    int b = blockIdx.z;
    int c0 = blockIdx.y * 32, n0 = blockIdx.x * 32;
    const float* xb = x + (size_t)b * CC * NN;
    #pragma unroll
    for (int i = threadIdx.y; i < 32; i += 8)
        tile[i][threadIdx.x] = xb[(size_t)(c0 + i) * NN + n0 + threadIdx.x];
    __syncthreads();
    float* xt = g_xT + (size_t)b * NN * CC;
    #pragma unroll
    for (int i = threadIdx.y; i < 32; i += 8)
        xt[(size_t)(n0 + i) * CC + c0 + threadIdx.x] = tile[threadIdx.x][i];
}

// ---------------- kNN + fused F1: one warp per query row ----------------
// Selection: register 4-list of u64 keys (d2bits<<32 | idx), REDUX-min rounds.
// During round `it`, lane `it` records the winner; afterwards lanes 0..29
// compute spherical features + W1 matvec in parallel (one neighbor per lane),
// write g_idx + g_h1, and accumulate BN1 moments (deterministic last-block
// finalize).
__global__ void __launch_bounds__(256) knn_f1_kernel(const float* __restrict__ xloc,
                                                     const float* __restrict__ W1,
                                                     const float* __restrict__ g1,
                                                     const float* __restrict__ b1) {
    const unsigned FULL = 0xffffffffu;
    const unsigned long long KMAX = 0xFFFFFFFFFFFFFFFFull;
    __shared__ float sW[36];
    __shared__ float2 red[8];
    __shared__ float tot[12];
    __shared__ bool s_last;
    int tid = threadIdx.x;
    if (tid < 36) sW[tid] = W1[tid];
    __syncthreads();

    int b = blockIdx.y;
    int warp = tid >> 5, lane = tid & 31;
    int n = blockIdx.x * 8 + warp;

    const float* px = xloc + (size_t)b * 3 * NN;
    const float* py = px + NN;
    const float* pz = px + 2 * NN;
    const float4* px4 = (const float4*)px;
    const float4* py4 = (const float4*)py;
    const float4* pz4 = (const float4*)pz;
    float cx = __ldg(px + n), cy = __ldg(py + n), cz = __ldg(pz + n);

    // sorted ascending 4-list in registers
    unsigned long long k0 = KMAX, k1 = KMAX, k2 = KMAX, k3 = KMAX;

    #pragma unroll 2
    for (int i = 0; i < 32; i++) {
        int base = i * 32 + lane;
        float4 X = __ldg(px4 + base);
        float4 Y = __ldg(py4 + base);
        float4 Z = __ldg(pz4 + base);
        #pragma unroll
        for (int j = 0; j < 4; j++) {
            float dx = ((const float*)&X)[j] - cx;
            float dy = ((const float*)&Y)[j] - cy;
            float dz = ((const float*)&Z)[j] - cz;
            float d2 = fmaf(dz, dz, fmaf(dy, dy, dx * dx));
            unsigned d2b = __float_as_uint(d2);
            if (d2b <= (unsigned)(k3 >> 32)) {   // fast reject (never skips a qualifier)
                unsigned long long key =
                    ((unsigned long long)d2b << 32) | (unsigned)(base * 4 + j);
                if (key < k3) {
                    if (key < k2) {
                        k3 = k2;
                        if (key < k1) { k2 = k1; if (key < k0) { k1 = k0; k0 = key; } else k1 = key; }
                        else k2 = key;
                    } else k3 = key;
                }
            }
        }
    }

    unsigned long long lastpop = 0;
    int outbase = (b * NN + n) * KK;
    int rec_idx = 0;  // lane `it` records round-it winner

    for (int it = 0; it < KK; it++) {
        unsigned hb = (unsigned)(k0 >> 32);
        unsigned minhb = __reduce_min_sync(FULL, hb);
        unsigned myidx = (hb == minhb) ? (unsigned)k0 : 0xFFFFFFFFu;
        unsigned widx = __reduce_min_sync(FULL, myidx);
        if (lane == it) rec_idx = (int)widx;
        // exactly one lane holds the global min key; it pops
        if (hb == minhb && (unsigned)k0 == widx) {
            lastpop = k0;
            k0 = k1; k1 = k2; k2 = k3; k3 = KMAX;
            if (k0 == KMAX) {
                // refill: rescan my candidates, keep 4 smallest keys > lastpop
                for (int i = 0; i < 32; i++) {
                    int base = i * 32 + lane;
                    float4 X = __ldg(px4 + base);
                    float4 Y = __ldg(py4 + base);
                    float4 Z = __ldg(pz4 + base);
                    #pragma unroll
                    for (int j = 0; j < 4; j++) {
                        float dx = ((const float*)&X)[j] - cx;
                        float dy = ((const float*)&Y)[j] - cy;
                        float dz = ((const float*)&Z)[j] - cz;
                        float d2 = fmaf(dz, dz, fmaf(dy, dy, dx * dx));
                        unsigned long long key =
                            ((unsigned long long)__float_as_uint(d2) << 32) | (unsigned)(base * 4 + j);
                        if (key > lastpop && key < k3) {
                            if (key < k2) {
                                k3 = k2;
                                if (key < k1) { k2 = k1; if (key < k0) { k1 = k0; k0 = key; } else k1 = key; }
                                else k2 = key;
                            } else k3 = key;
                        }
                    }
                }
            }
        }
    }

    // ---- fused F1: one neighbor per lane (lanes 0..29), data hot in L1 ----
    float sum[6] = {0,0,0,0,0,0}, ssq[6] = {0,0,0,0,0,0};
    if (lane < KK) {
        g_idx[outbase + lane] = rec_idx;
        float xr = __ldg(px + rec_idx) - cx;
        float yr = __ldg(py + rec_idx) - cy;
        float zr = __ldg(pz + rec_idx) - cz;
        float sxy2 = fmaf(yr, yr, xr * xr);
        float r2   = fmaf(zr, zr, sxy2);
        float rho  = sqrtf(fmaxf(r2, 1e-20f));
        float sxy  = sqrtf(fmaxf(sxy2, 1e-20f));
        bool deg_r = r2 < 1e-20f;
        bool deg_p = sxy2 < 1e-20f;
        float theta = atan2f(deg_r ? 0.f : zr, deg_r ? 1.f : sxy);
        float phi   = atan2f(deg_p ? 0.f : yr, deg_p ? 1.f : xr);
        float mean  = (rho + theta + phi) * (1.f / 3.f);
        float f[6] = { rho, theta, phi, rho - mean, theta - mean, phi - mean };
        #pragma unroll
        for (int j = 0; j < 6; j++) {
            float a = 0.f;
            #pragma unroll
            for (int i = 0; i < 6; i++) a = fmaf(sW[j * 6 + i], f[i], a);
            g_h1[(size_t)j * E_TOT + outbase + lane] = a;
            sum[j] = a;
            ssq[j] = a * a;
        }
    }

    // deterministic block reduction of BN1 moments
    int bid = blockIdx.y * (NN / 8) + blockIdx.x;
    #pragma unroll
    for (int j = 0; j < 6; j++) {
        float2 s = blockReduceSum2(sum[j], ssq[j], red);
        if (tid == 0) {
            g_part1[j * NBLKK + bid]       = s.x;
            g_part1[(6 + j) * NBLKK + bid] = s.y;
        }
    }
    if (tid == 0) {
        __threadfence();
        s_last = (atomicAdd(&g_cnt1, 1u) == NBLKK - 1);
    }
    __syncthreads();
    if (s_last) {
        finalize_bn(g_part1, NBLKK, 12, 6, 0, g1, b1, tot);
        if (tid == 0) g_cnt1 = 0;
    }
}

// ---------------- F2: bn1+lrelu -> a2 + fused BN2 stats ----------------
__global__ void __launch_bounds__(256) f2_kernel(const float* __restrict__ W2,
                                                 const float* __restrict__ g2,
                                                 const float* __restrict__ b2) {
    __shared__ float sW[18];
    __shared__ float sb[12];
    __shared__ float2 red[8];
    __shared__ float tot[12];
    __shared__ bool s_last;
    int tid = threadIdx.x;
    if (tid < 18) sW[tid] = W2[tid];
    if (tid < 12) sb[tid] = g_bn[tid];
    __syncthreads();

    float sum[3] = {0,0,0}, ssq[3] = {0,0,0};
    int e0 = blockIdx.x * EPB + tid * 4;

    float4 h4[6];
    #pragma unroll
    for (int j = 0; j < 6; j++)
        h4[j] = *(const float4*)(g_h1 + (size_t)j * E_TOT + e0);
    float4 a4[3];
    #pragma unroll
    for (int v = 0; v < 4; v++) {
        float y[6];
        #pragma unroll
        for (int j = 0; j < 6; j++)
            y[j] = lrelu(fmaf(((const float*)&h4[j])[v], sb[j], sb[6 + j]));
        #pragma unroll
        for (int j = 0; j < 3; j++) {
            float s = 0.f;
            #pragma unroll
            for (int i = 0; i < 6; i++) s = fmaf(sW[j * 6 + i], y[i], s);
            ((float*)&a4[j])[v] = s;
            sum[j] += s;
            ssq[j] = fmaf(s, s, ssq[j]);
        }
    }
    #pragma unroll
    for (int j = 0; j < 3; j++)
        *(float4*)(g_a2 + (size_t)j * E_TOT + e0) = a4[j];

    #pragma unroll
    for (int j = 0; j < 3; j++) {
        float2 s = blockReduceSum2(sum[j], ssq[j], red);
        if (tid == 0) {
            g_part2[j * NBLK2 + blockIdx.x]       = s.x;
            g_part2[(3 + j) * NBLK2 + blockIdx.x] = s.y;
        }
    }
    if (tid == 0) {
        __threadfence();
        s_last = (atomicAdd(&g_cnt2, 1u) == NBLK2 - 1);
    }
    __syncthreads();
    if (s_last) {
        finalize_bn(g_part2, NBLK2, 6, 3, 12, g2, b2, tot);
        if (tid == 0) g_cnt2 = 0;
    }
}

// ---------------- F3: bn2+lrelu -> a3 + fused BN3 stats ----------------
__global__ void __launch_bounds__(256) f3_kernel(const float* __restrict__ W3,
                                                 const float* __restrict__ g3,
                                                 const float* __restrict__ b3) {
    __shared__ float sW[3];
    __shared__ float sb[6];
    __shared__ float2 red[8];
    __shared__ float tot[12];
    __shared__ bool s_last;
    int tid = threadIdx.x;
    if (tid < 3) sW[tid] = W3[tid];
    if (tid < 6) sb[tid] = g_bn[12 + tid];
    __syncthreads();

    float sum = 0.f, ssq = 0.f;
    int e0 = blockIdx.x * EPB + tid * 4;

    float4 a4[3];
    #pragma unroll
    for (int j = 0; j < 3; j++)
        a4[j] = *(const float4*)(g_a2 + (size_t)j * E_TOT + e0);
    float4 s4;
    #pragma unroll
    for (int v = 0; v < 4; v++) {
        float s = 0.f;
        #pragma unroll
        for (int j = 0; j < 3; j++) {
            float y = lrelu(fmaf(((const float*)&a4[j])[v], sb[j], sb[3 + j]));
            s = fmaf(sW[j], y, s);
        }
        ((float*)&s4)[v] = s;
        sum += s;
        ssq = fmaf(s, s, ssq);
    }
    *(float4*)(g_a3 + e0) = s4;

    float2 t = blockReduceSum2(sum, ssq, red);
    if (tid == 0) {
        g_part3[blockIdx.x]         = t.x;
        g_part3[NBLK2 + blockIdx.x] = t.y;
    }
    if (tid == 0) {
        __threadfence();
        s_last = (atomicAdd(&g_cnt3, 1u) == NBLK2 - 1);
    }
    __syncthreads();
    if (s_last) {
        finalize_bn(g_part3, NBLK2, 2, 1, 18, g3, b3, tot);
        if (tid == 0) g_cnt3 = 0;
    }
}

// ---------------- F4: bn3+lrelu -> softmax -> gather -> out ----------------
__global__ void f4_kernel(float* __restrict__ out) {
    int gw = (blockIdx.x * blockDim.x + threadIdx.x) >> 5;  // global warp = point id
    int lane = threadIdx.x & 31;
    int b = gw >> 12, n = gw & (NN - 1);
    int base = gw * KK;

    float sc = g_bn[18], sh = g_bn[19];
    float logit = -FLT_MAX;
    int nb = 0;
    if (lane < KK) {
        float a = g_a3[base + lane];
        logit = lrelu(fmaf(a, sc, sh));
        nb = g_idx[base + lane];
    }
    float mx = logit;
    #pragma unroll
    for (int o = 16; o; o >>= 1) mx = fmaxf(mx, __shfl_xor_sync(0xffffffffu, mx, o));
    float ex = (lane < KK) ? expf(logit - mx) : 0.f;
    float s = ex;
    #pragma unroll
    for (int o = 16; o; o >>= 1) s += __shfl_xor_sync(0xffffffffu, s, o);
    float att = ex / s;

    const float* xTb = g_xT + (size_t)b * NN * CC;
    float acc0 = 0.f, acc1 = 0.f;
    #pragma unroll
    for (int kk = 0; kk < KK; kk++) {
        int   t = __shfl_sync(0xffffffffu, nb, kk);
        float a = __shfl_sync(0xffffffffu, att, kk);
        float2 v = *(const float2*)(xTb + (size_t)t * CC + lane * 2);
        acc0 = fmaf(a, v.x, acc0);
        acc1 = fmaf(a, v.y, acc1);
    }
    float2 c = *(const float2*)(xTb + (size_t)n * CC + lane * 2);
    float* ob = out + (size_t)b * CC * NN;
    ob[(size_t)(2 * lane)     * NN + n] = c.x + acc0;
    ob[(size_t)(2 * lane + 1) * NN + n] = c.y + acc1;
}

// ---------------- launch ----------------
extern "C" void kernel_launch(void* const* d_in, const int* in_sizes, int n_in,
                              void* d_out, int out_size) {
    const float* x_loc = (const float*)d_in[0];
    const float* x     = (const float*)d_in[1];
    const float* W1    = (const float*)d_in[2];
    const float* g1    = (const float*)d_in[3];
    const float* b1    = (const float*)d_in[4];
    const float* W2    = (const float*)d_in[5];
    const float* g2    = (const float*)d_in[6];
    const float* b2    = (const float*)d_in[7];
    const float* W3    = (const float*)d_in[8];
    const float* g3    = (const float*)d_in[9];
    const float* b3    = (const float*)d_in[10];
    float* out = (float*)d_out;

    transpose_kernel<<<dim3(NN / 32, CC / 32, BB), dim3(32, 8)>>>(x);
    knn_f1_kernel<<<dim3(NN / 8, BB), 256>>>(x_loc, W1, g1, b1);
    f2_kernel<<<NBLK2, 256>>>(W2, g2, b2);
    f3_kernel<<<NBLK2, 256>>>(W3, g3, b3);
    f4_kernel<<<(BB * NN) / 8, 256>>>(out);
}

// round 15
// speedup vs baseline: 1.2587x; 1.2587x over previous
#include <cuda_runtime.h>
#include <cuda_bf16.h>
#include <float.h>
#include <math.h>

// Problem constants
#define BB 8
#define NN 4096
#define CC 64
#define KK 30
#define E_TOT (BB*NN*KK)          // 983040
#define EPB   1024                // elements per block in F kernels (256 thr x 4)
#define NBLK2 (E_TOT/EPB)         // 960

// ---------------- scratch (device globals; no runtime allocation) ----------------
__device__ int   g_idx[E_TOT];                 // neighbor indices [B,N,K]
__device__ float g_h1[6*(size_t)E_TOT];        // layer1 pre-activations, SoA
__device__ float g_a2[3*(size_t)E_TOT];        // layer2 pre-activations, SoA
__device__ float g_a3[E_TOT];                  // layer3 pre-activations
__device__ float g_xT[(size_t)BB*NN*CC];       // x transposed to [B,N,C]
// partials transposed: [stat][block]
__device__ float g_part1[12*NBLK2];
__device__ float g_part2[6*NBLK2];
__device__ float g_part3[2*NBLK2];
__device__ float g_bn[20];  // [0:6) sc1 [6:12) sh1 [12:15) sc2 [15:18) sh2 [18] sc3 [19] sh3
__device__ unsigned g_cnt1 = 0, g_cnt2 = 0, g_cnt3 = 0;

// ---------------- helpers ----------------
__device__ __forceinline__ float2 blockReduceSum2(float a, float b, float2* sh) {
    #pragma unroll
    for (int o = 16; o; o >>= 1) {
        a += __shfl_down_sync(0xffffffffu, a, o);
        b += __shfl_down_sync(0xffffffffu, b, o);
    }
    int w = threadIdx.x >> 5;
    if ((threadIdx.x & 31) == 0) sh[w] = make_float2(a, b);
    __syncthreads();
    float2 r = make_float2(0.f, 0.f);
    if (w == 0) {
        if (threadIdx.x < 8) r = sh[threadIdx.x];
        #pragma unroll
        for (int o = 4; o; o >>= 1) {
            r.x += __shfl_down_sync(0xffffffffu, r.x, o);
            r.y += __shfl_down_sync(0xffffffffu, r.y, o);
        }
    }
    __syncthreads();
    return r;  // valid in thread 0
}

__device__ __forceinline__ float lrelu(float x) { return x > 0.f ? x : 0.2f * x; }

// Last-block finalize: reduce `nstat` partial rows of length `nblk` (fixed order,
// deterministic), compute BN scale/shift for `nch` channels into g_bn[off..].
__device__ __forceinline__ void finalize_bn(const float* part, int nblk, int nstat,
                                            int nch, int off,
                                            const float* gamma, const float* beta,
                                            float* tot /* shared[12] */) {
    __threadfence();
    int w = threadIdx.x >> 5, lane = threadIdx.x & 31;
    for (int st = w; st < nstat; st += 8) {
        const float* p = part + (size_t)st * nblk;
        float s = 0.f;
        for (int i = lane; i < nblk; i += 32) s += p[i];
        #pragma unroll
        for (int o = 16; o; o >>= 1) s += __shfl_down_sync(0xffffffffu, s, o);
        if (lane == 0) tot[st] = s;
    }
    __syncthreads();
    if (threadIdx.x < nch) {
        float inv = 1.f / (float)E_TOT;
        float mu  = tot[threadIdx.x] * inv;
        float var = tot[nch + threadIdx.x] * inv - mu * mu;
        float sc  = gamma[threadIdx.x] * rsqrtf(var + 1e-5f);
        g_bn[off + threadIdx.x] = sc;
        g_bn[off + nch + threadIdx.x] = beta[threadIdx.x] - mu * sc;
    }
}

// ---------------- transpose x: [B,C,N] -> [B,N,C] ----------------
__global__ void transpose_kernel(const float* __restrict__ x) {
    __shared__ float tile[32][33];
    int b = blockIdx.z;
    int c0 = blockIdx.y * 32, n0 = blockIdx.x * 32;
    const float* xb = x + (size_t)b * CC * NN;
    #pragma unroll
    for (int i = threadIdx.y; i < 32; i += 8)
        tile[i][threadIdx.x] = xb[(size_t)(c0 + i) * NN + n0 + threadIdx.x];
    __syncthreads();
    float* xt = g_xT + (size_t)b * NN * CC;
    #pragma unroll
    for (int i = threadIdx.y; i < 32; i += 8)
        xt[(size_t)(n0 + i) * CC + c0 + threadIdx.x] = tile[threadIdx.x][i];
}

// ---------------- kNN: one warp per row; branch-free 32-bit 4-list w/ carried idx ----
// Exact lexicographic (d2bits, idx) selection:
//  - within-lane list sorted by value; equal values self-order by ascending idx
//    (scan order + strict-< insert; rejected equal candidates are dominated forever)
//  - rounds: REDUX umin on head values, then REDUX umin on idx among tied lanes
//  - refill excludes popped entries by (val,idx) lexicographic comparison
__global__ void __launch_bounds__(256) knn_kernel(const float* __restrict__ xloc) {
    const unsigned FULL = 0xffffffffu;
    const unsigned SENT = 0xffffffffu;  // > any finite d2 bit pattern
    int b = blockIdx.y;
    int warp = threadIdx.x >> 5, lane = threadIdx.x & 31;
    int n = blockIdx.x * 8 + warp;

    const float* px = xloc + (size_t)b * 3 * NN;
    const float* py = px + NN;
    const float* pz = px + 2 * NN;
    const float4* px4 = (const float4*)px;
    const float4* py4 = (const float4*)py;
    const float4* pz4 = (const float4*)pz;
    float cx = __ldg(px + n), cy = __ldg(py + n), cz = __ldg(pz + n);

    // ascending 4-list: values + parallel indices
    unsigned v0 = SENT, v1 = SENT, v2 = SENT, v3 = SENT;
    unsigned i0 = SENT, i1 = SENT, i2 = SENT, i3 = SENT;

    #pragma unroll 2
    for (int i = 0; i < 32; i++) {
        int base = i * 32 + lane;
        float4 X = __ldg(px4 + base);
        float4 Y = __ldg(py4 + base);
        float4 Z = __ldg(pz4 + base);
        #pragma unroll
        for (int j = 0; j < 4; j++) {
            float dx = ((const float*)&X)[j] - cx;
            float dy = ((const float*)&Y)[j] - cy;
            float dz = ((const float*)&Z)[j] - cz;
            float d2 = fmaf(dz, dz, fmaf(dy, dy, dx * dx));
            unsigned d2b = __float_as_uint(d2);
            unsigned m = (unsigned)(base * 4 + j);
            if (d2b < v3) {  // gate (strict: equal-to-v3 is dominated)
                bool c0 = d2b < v0, c1 = d2b < v1, c2 = d2b < v2;
                v3 = c2 ? v2 : d2b;  i3 = c2 ? i2 : m;
                v2 = c1 ? v1 : (c2 ? d2b : v2);  i2 = c1 ? i1 : (c2 ? m : i2);
                v1 = c0 ? v0 : (c1 ? d2b : v1);  i1 = c0 ? i0 : (c1 ? m : i1);
                v0 = c0 ? d2b : v0;  i0 = c0 ? m : i0;
            }
        }
    }

    unsigned lastv = 0, lasti = 0;
    int outbase = (b * NN + n) * KK;

    for (int it = 0; it < KK; it++) {
        unsigned minv = __reduce_min_sync(FULL, v0);
        unsigned cand = (v0 == minv) ? i0 : 0xFFFFFFFFu;
        unsigned widx = __reduce_min_sync(FULL, cand);
        if (lane == 0) g_idx[outbase + it] = (int)widx;
        // unique winner (indices distinct): it pops
        if (v0 == minv && i0 == widx) {
            lastv = v0; lasti = i0;
            v0 = v1; i0 = i1; v1 = v2; i1 = i2; v2 = v3; i2 = i3;
            v3 = SENT; i3 = SENT;
            if (v0 == SENT) {
                // refill: rescan, keep 4 smallest with (val,idx) > (lastv,lasti)
                for (int i = 0; i < 32; i++) {
                    int base = i * 32 + lane;
                    float4 X = __ldg(px4 + base);
                    float4 Y = __ldg(py4 + base);
                    float4 Z = __ldg(pz4 + base);
                    #pragma unroll
                    for (int j = 0; j < 4; j++) {
                        float dx = ((const float*)&X)[j] - cx;
                        float dy = ((const float*)&Y)[j] - cy;
                        float dz = ((const float*)&Z)[j] - cz;
                        float d2 = fmaf(dz, dz, fmaf(dy, dy, dx * dx));
                        unsigned d2b = __float_as_uint(d2);
                        unsigned m = (unsigned)(base * 4 + j);
                        bool fresh = (d2b > lastv) || (d2b == lastv && m > lasti);
                        if (fresh && d2b < v3) {
                            bool c0 = d2b < v0, c1 = d2b < v1, c2 = d2b < v2;
                            v3 = c2 ? v2 : d2b;  i3 = c2 ? i2 : m;
                            v2 = c1 ? v1 : (c2 ? d2b : v2);  i2 = c1 ? i1 : (c2 ? m : i2);
                            v1 = c0 ? v0 : (c1 ? d2b : v1);  i1 = c0 ? i0 : (c1 ? m : i1);
                            v0 = c0 ? d2b : v0;  i0 = c0 ? m : i0;
                        }
                    }
                }
            }
        }
    }
}

// ---------------- F1: spherical features -> h1 + fused BN1 stats ----------------
__global__ void __launch_bounds__(256) f1_kernel(const float* __restrict__ xloc,
                                                 const float* __restrict__ W1,
                                                 const float* __restrict__ g1,
                                                 const float* __restrict__ b1) {
    __shared__ float sW[36];
    __shared__ float2 red[8];
    __shared__ float tot[12];
    __shared__ bool s_last;
    int tid = threadIdx.x;
    if (tid < 36) sW[tid] = W1[tid];
    __syncthreads();

    float sum[6] = {0,0,0,0,0,0}, ssq[6] = {0,0,0,0,0,0};
    int e0 = blockIdx.x * EPB + tid * 4;  // 4 consecutive elements
    int4 idx4 = *(const int4*)(g_idx + e0);
    float h4[6][4];
    #pragma unroll
    for (int v = 0; v < 4; v++) {
        int e = e0 + v;
        int b = e / (NN * KK);
        int rem = e - b * (NN * KK);
        int n = rem / KK;
        int idx = ((const int*)&idx4)[v];
        const float* xb = xloc + (size_t)b * 3 * NN;
        float cx = __ldg(xb + n), cy = __ldg(xb + NN + n), cz = __ldg(xb + 2*NN + n);
        float xr = __ldg(xb + idx) - cx, yr = __ldg(xb + NN + idx) - cy, zr = __ldg(xb + 2*NN + idx) - cz;

        float sxy2 = fmaf(yr, yr, xr * xr);
        float r2   = fmaf(zr, zr, sxy2);
        float rho  = sqrtf(fmaxf(r2, 1e-20f));
        float sxy  = sqrtf(fmaxf(sxy2, 1e-20f));
        bool deg_r = r2 < 1e-20f;
        bool deg_p = sxy2 < 1e-20f;
        float theta = atan2f(deg_r ? 0.f : zr, deg_r ? 1.f : sxy);
        float phi   = atan2f(deg_p ? 0.f : yr, deg_p ? 1.f : xr);
        float mean  = (rho + theta + phi) * (1.f / 3.f);
        float f[6] = { rho, theta, phi, rho - mean, theta - mean, phi - mean };

        #pragma unroll
        for (int j = 0; j < 6; j++) {
            float a = 0.f;
            #pragma unroll
            for (int i = 0; i < 6; i++) a = fmaf(sW[j * 6 + i], f[i], a);
            h4[j][v] = a;
            sum[j] += a;
            ssq[j] = fmaf(a, a, ssq[j]);
        }
    }
    #pragma unroll
    for (int j = 0; j < 6; j++)
        *(float4*)(g_h1 + (size_t)j * E_TOT + e0) =
            make_float4(h4[j][0], h4[j][1], h4[j][2], h4[j][3]);

    #pragma unroll
    for (int j = 0; j < 6; j++) {
        float2 s = blockReduceSum2(sum[j], ssq[j], red);
        if (tid == 0) {
            g_part1[j * NBLK2 + blockIdx.x]       = s.x;
            g_part1[(6 + j) * NBLK2 + blockIdx.x] = s.y;
        }
    }
    if (tid == 0) {
        __threadfence();
        s_last = (atomicAdd(&g_cnt1, 1u) == NBLK2 - 1);
    }
    __syncthreads();
    if (s_last) {
        finalize_bn(g_part1, NBLK2, 12, 6, 0, g1, b1, tot);
        if (tid == 0) g_cnt1 = 0;
    }
}

// ---------------- F2: bn1+lrelu -> a2 + fused BN2 stats ----------------
__global__ void __launch_bounds__(256) f2_kernel(const float* __restrict__ W2,
                                                 const float* __restrict__ g2,
                                                 const float* __restrict__ b2) {
    __shared__ float sW[18];
    __shared__ float sb[12];
    __shared__ float2 red[8];
    __shared__ float tot[12];
    __shared__ bool s_last;
    int tid = threadIdx.x;
    if (tid < 18) sW[tid] = W2[tid];
    if (tid < 12) sb[tid] = g_bn[tid];
    __syncthreads();

    float sum[3] = {0,0,0}, ssq[3] = {0,0,0};
    int e0 = blockIdx.x * EPB + tid * 4;

    float4 h4[6];
    #pragma unroll
    for (int j = 0; j < 6; j++)
        h4[j] = *(const float4*)(g_h1 + (size_t)j * E_TOT + e0);
    float4 a4[3];
    #pragma unroll
    for (int v = 0; v < 4; v++) {
        float y[6];
        #pragma unroll
        for (int j = 0; j < 6; j++)
            y[j] = lrelu(fmaf(((const float*)&h4[j])[v], sb[j], sb[6 + j]));
        #pragma unroll
        for (int j = 0; j < 3; j++) {
            float s = 0.f;
            #pragma unroll
            for (int i = 0; i < 6; i++) s = fmaf(sW[j * 6 + i], y[i], s);
            ((float*)&a4[j])[v] = s;
            sum[j] += s;
            ssq[j] = fmaf(s, s, ssq[j]);
        }
    }
    #pragma unroll
    for (int j = 0; j < 3; j++)
        *(float4*)(g_a2 + (size_t)j * E_TOT + e0) = a4[j];

    #pragma unroll
    for (int j = 0; j < 3; j++) {
        float2 s = blockReduceSum2(sum[j], ssq[j], red);
        if (tid == 0) {
            g_part2[j * NBLK2 + blockIdx.x]       = s.x;
            g_part2[(3 + j) * NBLK2 + blockIdx.x] = s.y;
        }
    }
    if (tid == 0) {
        __threadfence();
        s_last = (atomicAdd(&g_cnt2, 1u) == NBLK2 - 1);
    }
    __syncthreads();
    if (s_last) {
        finalize_bn(g_part2, NBLK2, 6, 3, 12, g2, b2, tot);
        if (tid == 0) g_cnt2 = 0;
    }
}

// ---------------- F3: bn2+lrelu -> a3 + fused BN3 stats ----------------
__global__ void __launch_bounds__(256) f3_kernel(const float* __restrict__ W3,
                                                 const float* __restrict__ g3,
                                                 const float* __restrict__ b3) {
    __shared__ float sW[3];
    __shared__ float sb[6];
    __shared__ float2 red[8];
    __shared__ float tot[12];
    __shared__ bool s_last;
    int tid = threadIdx.x;
    if (tid < 3) sW[tid] = W3[tid];
    if (tid < 6) sb[tid] = g_bn[12 + tid];
    __syncthreads();

    float sum = 0.f, ssq = 0.f;
    int e0 = blockIdx.x * EPB + tid * 4;

    float4 a4[3];
    #pragma unroll
    for (int j = 0; j < 3; j++)
        a4[j] = *(const float4*)(g_a2 + (size_t)j * E_TOT + e0);
    float4 s4;
    #pragma unroll
    for (int v = 0; v < 4; v++) {
        float s = 0.f;
        #pragma unroll
        for (int j = 0; j < 3; j++) {
            float y = lrelu(fmaf(((const float*)&a4[j])[v], sb[j], sb[3 + j]));
            s = fmaf(sW[j], y, s);
        }
        ((float*)&s4)[v] = s;
        sum += s;
        ssq = fmaf(s, s, ssq);
    }
    *(float4*)(g_a3 + e0) = s4;

    float2 t = blockReduceSum2(sum, ssq, red);
    if (tid == 0) {
        g_part3[blockIdx.x]         = t.x;
        g_part3[NBLK2 + blockIdx.x] = t.y;
    }
    if (tid == 0) {
        __threadfence();
        s_last = (atomicAdd(&g_cnt3, 1u) == NBLK2 - 1);
    }
    __syncthreads();
    if (s_last) {
        finalize_bn(g_part3, NBLK2, 2, 1, 18, g3, b3, tot);
        if (tid == 0) g_cnt3 = 0;
    }
}

// ---------------- F4: bn3+lrelu -> softmax -> gather -> out ----------------
__global__ void f4_kernel(float* __restrict__ out) {
    int gw = (blockIdx.x * blockDim.x + threadIdx.x) >> 5;  // global warp = point id
    int lane = threadIdx.x & 31;
    int b = gw >> 12, n = gw & (NN - 1);
    int base = gw * KK;

    float sc = g_bn[18], sh = g_bn[19];
    float logit = -FLT_MAX;
    int nb = 0;
    if (lane < KK) {
        float a = g_a3[base + lane];
        logit = lrelu(fmaf(a, sc, sh));
        nb = g_idx[base + lane];
    }
    float mx = logit;
    #pragma unroll
    for (int o = 16; o; o >>= 1) mx = fmaxf(mx, __shfl_xor_sync(0xffffffffu, mx, o));
    float ex = (lane < KK) ? expf(logit - mx) : 0.f;
    float s = ex;
    #pragma unroll
    for (int o = 16; o; o >>= 1) s += __shfl_xor_sync(0xffffffffu, s, o);
    float att = ex / s;

    const float* xTb = g_xT + (size_t)b * NN * CC;
    float acc0 = 0.f, acc1 = 0.f;
    #pragma unroll
    for (int kk = 0; kk < KK; kk++) {
        int   t = __shfl_sync(0xffffffffu, nb, kk);
        float a = __shfl_sync(0xffffffffu, att, kk);
        float2 v = *(const float2*)(xTb + (size_t)t * CC + lane * 2);
        acc0 = fmaf(a, v.x, acc0);
        acc1 = fmaf(a, v.y, acc1);
    }
    float2 c = *(const float2*)(xTb + (size_t)n * CC + lane * 2);
    float* ob = out + (size_t)b * CC * NN;
    ob[(size_t)(2 * lane)     * NN + n] = c.x + acc0;
    ob[(size_t)(2 * lane + 1) * NN + n] = c.y + acc1;
}

// ---------------- launch ----------------
extern "C" void kernel_launch(void* const* d_in, const int* in_sizes, int n_in,
                              void* d_out, int out_size) {
    const float* x_loc = (const float*)d_in[0];
    const float* x     = (const float*)d_in[1];
    const float* W1    = (const float*)d_in[2];
    const float* g1    = (const float*)d_in[3];
    const float* b1    = (const float*)d_in[4];
    const float* W2    = (const float*)d_in[5];
    const float* g2    = (const float*)d_in[6];
    const float* b2    = (const float*)d_in[7];
    const float* W3    = (const float*)d_in[8];
    const float* g3    = (const float*)d_in[9];
    const float* b3    = (const float*)d_in[10];
    float* out = (float*)d_out;

    transpose_kernel<<<dim3(NN / 32, CC / 32, BB), dim3(32, 8)>>>(x);
    knn_kernel<<<dim3(NN / 8, BB), 256>>>(x_loc);
    f1_kernel<<<NBLK2, 256>>>(x_loc, W1, g1, b1);
    f2_kernel<<<NBLK2, 256>>>(W2, g2, b2);
    f3_kernel<<<NBLK2, 256>>>(W3, g3, b3);
    f4_kernel<<<(BB * NN) / 8, 256>>>(out);
}